// round 9
// baseline (speedup 1.0000x reference)
#include <cuda_runtime.h>
#include <math.h>
#include <stdint.h>

// ---------------- problem constants ----------------
#define T_TOK 2048      // B*S
#define HDIM  1024
#define SSEQ  1024
#define BB    2
#define NHQ   16
#define NKVH  4
#define NEXP  64
#define TOPK  8
#define IE    512
#define IS    1408

// ---------------- scratch arena (static, no allocs) ----------------
static const size_t OFF_X    = 0;          // [T,1024]
static const size_t OFF_QKV  = 2097152;    // [T,1536]  q|k|v packed
static const size_t OFF_ATTN = 5242880;    // [T,1024]
static const size_t OFF_H    = 7340032;    // [T,1024]
static const size_t OFF_Y    = 9437184;    // [T,1024]
static const size_t OFF_MOE  = 11534336;   // [T,1024]
static const size_t OFF_SINT = 13631488;   // [T,1408]
static const size_t OFF_LOG  = 16515072;   // [T,64]
static const size_t OFF_G    = 16646144;   // [T]
static const size_t OFF_WTS  = 16648192;   // [E,2048]
static const size_t OFF_INT  = 16779264;   // [E,2048,512]
__device__ float g_arena[83888128];
__device__ int   g_iarena[131136];         // toks [E,2048] then counts[64]

// ---------------- helpers ----------------
__device__ __forceinline__ float block_sum_256(float v) {
    __shared__ float red[8];
    #pragma unroll
    for (int o = 16; o; o >>= 1) v += __shfl_xor_sync(0xffffffffu, v, o);
    if ((threadIdx.x & 31) == 0) red[threadIdx.x >> 5] = v;
    __syncthreads();
    if (threadIdx.x == 0) {
        float s = 0.f;
        #pragma unroll
        for (int i = 0; i < 8; i++) s += red[i];
        red[0] = s;
    }
    __syncthreads();
    return red[0];
}

__device__ __forceinline__ uint32_t f2tf32(float f) {
    uint32_t u;
    asm("cvt.rna.tf32.f32 %0, %1;" : "=r"(u) : "f"(f));
    return u;
}
__device__ __forceinline__ float roundtf(float f) { return __uint_as_float(f2tf32(f)); }

#define MMA_TF32(d, a, b)                                                      \
    asm volatile("mma.sync.aligned.m16n8k8.row.col.f32.tf32.tf32.f32 "         \
                 "{%0,%1,%2,%3}, {%4,%5,%6,%7}, {%8,%9}, {%0,%1,%2,%3};"       \
                 : "+f"(d[0]), "+f"(d[1]), "+f"(d[2]), "+f"(d[3])              \
                 : "r"(a[0]), "r"(a[1]), "r"(a[2]), "r"(a[3]),                 \
                   "r"(b[0]), "r"(b[1]))

__device__ __forceinline__ void cpasync16(uint32_t dst, const float* src, int sz) {
    asm volatile("cp.async.cg.shared.global [%0], [%1], 16, %2;"
                 :: "r"(dst), "l"(src), "r"(sz));
}
#define CP_COMMIT() asm volatile("cp.async.commit_group;")
#define CP_WAIT0()  asm volatile("cp.async.wait_group 0;")
#define CP_WAIT1()  asm volatile("cp.async.wait_group 1;")

// ---------------- elementwise / norm kernels ----------------
__global__ void zero_counts_kernel(int* counts) { counts[threadIdx.x] = 0; }

__global__ void rmsnorm_kernel(const float* __restrict__ x, const float* __restrict__ w,
                               float* __restrict__ out) {
    int t = blockIdx.x;
    const float* xr = x + (size_t)t * HDIM;
    float s = 0.f;
    for (int i = threadIdx.x; i < HDIM; i += 256) { float v = xr[i]; s += v * v; }
    s = block_sum_256(s);
    float inv = rsqrtf(s * (1.0f / HDIM) + 1e-6f);
    float* orow = out + (size_t)t * HDIM;
    // pre-round to tf32 grid: this buffer feeds tensor-core GEMMs as A
    for (int i = threadIdx.x; i < HDIM; i += 256) orow[i] = roundtf(xr[i] * inv * w[i]);
}

__global__ void sgate_kernel(const float* __restrict__ y, const float* __restrict__ shw,
                             float* __restrict__ g) {
    int t = blockIdx.x;
    const float* yr = y + (size_t)t * HDIM;
    float s = 0.f;
    for (int i = threadIdx.x; i < HDIM; i += 256) s += yr[i] * shw[i];
    s = block_sum_256(s);
    if (threadIdx.x == 0) g[t] = 1.0f / (1.0f + expf(-s));
}

__global__ void rope_kernel(float* __restrict__ qkv) {
    __shared__ float cs[32], sn[32];
    int t = blockIdx.x;
    int s = t & (SSEQ - 1);
    if (threadIdx.x < 32) {
        double inv = exp(-(double)threadIdx.x / 32.0 * log(1000000.0));
        double ang = (double)s * inv;
        cs[threadIdx.x] = (float)cos(ang);
        sn[threadIdx.x] = (float)sin(ang);
    }
    __syncthreads();
    float* base = qkv + (size_t)t * 1536;
    for (int w = threadIdx.x; w < 20 * 32; w += blockDim.x) {
        int hh = w >> 5, i = w & 31;
        float* p = base + (hh < 16 ? hh * 64 : 1024 + (hh - 16) * 64);
        float x1 = p[i], x2 = p[i + 32];
        float c = cs[i], s2 = sn[i];
        p[i]      = x1 * c - x2 * s2;
        p[i + 32] = x2 * c + x1 * s2;
    }
}

__global__ void add_kernel(const float* __restrict__ a, const float* __restrict__ b,
                           float* __restrict__ o, int n) {
    for (int i = blockIdx.x * blockDim.x + threadIdx.x; i < n; i += gridDim.x * blockDim.x)
        o[i] = a[i] + b[i];
}

// ---------------- SIMT NT GEMM (router logits only, N=64) ----------------
__global__ void __launch_bounds__(256) gemm_nt_kernel(
    const float* __restrict__ A, int lda,
    const float* __restrict__ B, int ldb,
    float* __restrict__ C, int ldc,
    int M, int N, int K)
{
    __shared__ float As[16][128];
    __shared__ float Bs[16][64];
    const int mb = blockIdx.y * 128;
    const int nb = blockIdx.x * 64;
    const int tid = threadIdx.x;
    const int tm = (tid >> 4) * 8;
    const int tn = (tid & 15) * 4;
    float acc[8][4];
    #pragma unroll
    for (int i = 0; i < 8; i++)
        #pragma unroll
        for (int j = 0; j < 4; j++) acc[i][j] = 0.f;

    for (int kb = 0; kb < K; kb += 16) {
        #pragma unroll
        for (int i = 0; i < 2; i++) {
            int f4 = tid + i * 256;
            int m = f4 >> 2, k4 = (f4 & 3) << 2;
            float4 v = make_float4(0.f, 0.f, 0.f, 0.f);
            int gm = mb + m;
            if (gm < M) v = *(const float4*)(A + (size_t)gm * lda + kb + k4);
            As[k4][m] = v.x; As[k4 + 1][m] = v.y; As[k4 + 2][m] = v.z; As[k4 + 3][m] = v.w;
        }
        {
            int n = tid >> 2, k4 = (tid & 3) << 2;
            int gn = nb + n;
            float4 v = make_float4(0.f, 0.f, 0.f, 0.f);
            if (gn < N) v = *(const float4*)(B + (size_t)gn * ldb + kb + k4);
            Bs[k4][n] = v.x; Bs[k4 + 1][n] = v.y; Bs[k4 + 2][n] = v.z; Bs[k4 + 3][n] = v.w;
        }
        __syncthreads();
        #pragma unroll
        for (int k = 0; k < 16; k++) {
            float4 a0 = *(const float4*)&As[k][tm];
            float4 a1 = *(const float4*)&As[k][tm + 4];
            float4 b  = *(const float4*)&Bs[k][tn];
            float av[8] = {a0.x, a0.y, a0.z, a0.w, a1.x, a1.y, a1.z, a1.w};
            float bv[4] = {b.x, b.y, b.z, b.w};
            #pragma unroll
            for (int i = 0; i < 8; i++)
                #pragma unroll
                for (int j = 0; j < 4; j++) acc[i][j] += av[i] * bv[j];
        }
        __syncthreads();
    }
    #pragma unroll
    for (int i = 0; i < 8; i++) {
        int gm = mb + tm + i;
        if (gm >= M) break;
        #pragma unroll
        for (int j = 0; j < 4; j++) {
            int gn = nb + tn + j;
            if (gn < N) C[(size_t)gm * ldc + gn] = acc[i][j];
        }
    }
}

// ---------------- tf32 tensor-core GEMM, 128x128 block, 512 thr, 3-stage cp.async ----------------
// BN: 0 = B is [K,N] n-contiguous (NN), 1 = B is [N,K] k-contiguous (NT)
// AMODE: 0 = plain A rows, 1 = gather via toks, 2 = expert slot rows
// EPI: 0 = C = res + scale*(acc+bias); 1 = C = tf32(silu(C)*acc); 2 = atomicAdd(moe, w*acc)
// QKV: 1 = select B/bias by output-column range (q|k|v packed, N=1536)
// A must be pre-rounded to tf32; B is cvt.rna'd on fragment load.
#define KC     16
#define APAD   20      // row stride (words) for k-contiguous tiles
#define ASTAGE 2560    // 128*20 words per stage
#define BPADN  136     // row stride for NN [16][136]

template<int BN, int AMODE, int EPI, int QKV>
__global__ void __launch_bounds__(512) mma_kernel(
    const float* __restrict__ A, int lda, size_t strideAe,
    const float* __restrict__ B, int ldb, size_t strideBe,
    const float* __restrict__ B2, const float* __restrict__ B3,
    const float* __restrict__ bias, const float* __restrict__ bias2,
    const float* __restrict__ bias3,
    const float* __restrict__ res, int ldres,
    const float* __restrict__ scale,
    const int* __restrict__ toks, const int* __restrict__ counts,
    const float* __restrict__ wts,
    float* __restrict__ C, int ldc, size_t strideCe,
    int M, int N, int K)
{
    const int e = blockIdx.z;
    int bound = M;
    if (AMODE != 0) bound = counts[e];
    const int mb = blockIdx.y * 128;
    if (mb >= bound) return;
    const int nb = blockIdx.x * 128;
    if (AMODE == 2) A += (size_t)e * strideAe;
    B += (size_t)e * strideBe;
    C += (size_t)e * strideCe;

    // QKV column-range weight select
    const float* Bw = B;
    const float* bi = bias;
    int rowoff = 0;
    if (QKV) {
        if (nb >= 1280)      { Bw = B3; bi = bias3; rowoff = 1280; }
        else if (nb >= 1024) { Bw = B2; bi = bias2; rowoff = 1024; }
    }

    __shared__ float As[3][ASTAGE];
    __shared__ float Bs[3][ASTAGE];

    const int tid = threadIdx.x;
    const int wid = tid >> 5, lane = tid & 31;
    const int g = lane >> 2, tg = lane & 3;
    const int wm = (wid & 3) * 32, wn = (wid >> 2) * 32;

    const uint32_t smA = (uint32_t)__cvta_generic_to_shared(&As[0][0]);
    const uint32_t smB = (uint32_t)__cvta_generic_to_shared(&Bs[0][0]);

    // ---- per-thread cp.async descriptors: 1 A chunk + 1 B chunk ----
    const float* asrc; int asz; uint32_t adst;
    {
        int m = tid >> 2, kq = tid & 3;
        int gm = mb + m;
        bool valid = gm < bound;
        int row = valid ? gm : 0;
        if (AMODE == 1) row = valid ? toks[e * T_TOK + gm] : 0;
        asrc = A + (size_t)row * lda + kq * 4;
        asz = valid ? 16 : 0;
        adst = smA + (uint32_t)(m * APAD + kq * 4) * 4u;
    }
    const float* bsrc; uint32_t bdst;
    long bstep;
    {
        if (BN == 1) {
            int n = tid >> 2, kq = tid & 3;
            bsrc = Bw + (size_t)(nb + n - rowoff) * ldb + kq * 4;
            bdst = smB + (uint32_t)(n * APAD + kq * 4) * 4u;
        } else {
            int kk = tid >> 5, n4 = (tid & 31) << 2;
            bsrc = B + (size_t)kk * ldb + nb + n4;
            bdst = smB + (uint32_t)(kk * BPADN + n4) * 4u;
        }
    }
    bstep = (BN == 1) ? KC : (long)KC * ldb;

    float acc[2][4][4];
    #pragma unroll
    for (int mt = 0; mt < 2; mt++)
        #pragma unroll
        for (int nt = 0; nt < 4; nt++)
            #pragma unroll
            for (int q = 0; q < 4; q++) acc[mt][nt][q] = 0.f;

    const int niter = K / KC;

    // prologue: stages 0 and 1
    #pragma unroll
    for (int st = 0; st < 2; st++) {
        uint32_t soff = (uint32_t)(st * ASTAGE * 4);
        cpasync16(adst + soff, asrc, asz);
        cpasync16(bdst + soff, bsrc, 16);
        CP_COMMIT();
        asrc += KC; bsrc += bstep;
    }

    for (int it = 0; it < niter; it++) {
        const int s = it % 3;
        if (it + 1 < niter) CP_WAIT1(); else CP_WAIT0();
        __syncthreads();
        if (it + 2 < niter) {
            const uint32_t soff = (uint32_t)(((it + 2) % 3) * ASTAGE * 4);
            cpasync16(adst + soff, asrc, asz);
            cpasync16(bdst + soff, bsrc, 16);
            CP_COMMIT();
            asrc += KC; bsrc += bstep;
        }
        // compute 2 k-steps of 8
        #pragma unroll
        for (int ks = 0; ks < KC; ks += 8) {
            uint32_t af[2][4], bf[4][2];
            #pragma unroll
            for (int mt = 0; mt < 2; mt++) {
                int r = wm + mt * 16 + g;
                af[mt][0] = __float_as_uint(As[s][r * APAD + ks + tg]);
                af[mt][1] = __float_as_uint(As[s][(r + 8) * APAD + ks + tg]);
                af[mt][2] = __float_as_uint(As[s][r * APAD + ks + tg + 4]);
                af[mt][3] = __float_as_uint(As[s][(r + 8) * APAD + ks + tg + 4]);
            }
            #pragma unroll
            for (int nt = 0; nt < 4; nt++) {
                int c = wn + nt * 8 + g;
                if (BN == 1) {
                    bf[nt][0] = f2tf32(Bs[s][c * APAD + ks + tg]);
                    bf[nt][1] = f2tf32(Bs[s][c * APAD + ks + tg + 4]);
                } else {
                    bf[nt][0] = f2tf32(Bs[s][(ks + tg) * BPADN + c]);
                    bf[nt][1] = f2tf32(Bs[s][(ks + tg + 4) * BPADN + c]);
                }
            }
            #pragma unroll
            for (int mt = 0; mt < 2; mt++)
                #pragma unroll
                for (int nt = 0; nt < 4; nt++)
                    MMA_TF32(acc[mt][nt], af[mt], bf[nt]);
        }
        __syncthreads();
    }

    // ---- epilogue ----
    #pragma unroll
    for (int mt = 0; mt < 2; mt++) {
        int rbase = mb + wm + mt * 16 + g;
        #pragma unroll
        for (int half = 0; half < 2; half++) {
            int rr = rbase + half * 8;
            if (rr >= bound) continue;
            if (EPI == 2) {
                int t = toks[e * T_TOK + rr];
                float w = wts[e * T_TOK + rr];
                float* mp = C + (size_t)t * ldc;
                #pragma unroll
                for (int nt = 0; nt < 4; nt++) {
                    int c = nb + wn + nt * 8 + 2 * tg;
                    atomicAdd(&mp[c],     w * acc[mt][nt][half * 2 + 0]);
                    atomicAdd(&mp[c + 1], w * acc[mt][nt][half * 2 + 1]);
                }
            } else if (EPI == 1) {
                float* cp = C + (size_t)rr * ldc;
                #pragma unroll
                for (int nt = 0; nt < 4; nt++) {
                    int c = nb + wn + nt * 8 + 2 * tg;
                    float2 p = *(float2*)&cp[c];
                    float v0 = p.x / (1.0f + expf(-p.x)) * acc[mt][nt][half * 2 + 0];
                    float v1 = p.y / (1.0f + expf(-p.y)) * acc[mt][nt][half * 2 + 1];
                    *(float2*)&cp[c] = make_float2(roundtf(v0), roundtf(v1));
                }
            } else {
                float sc = scale ? scale[rr] : 1.f;
                float* cp = C + (size_t)rr * ldc;
                const float* rp = res ? res + (size_t)rr * ldres : nullptr;
                #pragma unroll
                for (int nt = 0; nt < 4; nt++) {
                    int c = nb + wn + nt * 8 + 2 * tg;
                    float v0 = acc[mt][nt][half * 2 + 0];
                    float v1 = acc[mt][nt][half * 2 + 1];
                    if (bi) { v0 += bi[c - rowoff]; v1 += bi[c + 1 - rowoff]; }
                    v0 *= sc; v1 *= sc;
                    if (rp) { v0 += rp[c]; v1 += rp[c + 1]; }
                    *(float2*)&cp[c] = make_float2(v0, v1);
                }
            }
        }
    }
}

// ---------------- router top-k ----------------
__global__ void router_kernel(const float* __restrict__ logits, int* __restrict__ counts,
                              int* __restrict__ toks, float* __restrict__ wts) {
    int t = blockIdx.x * blockDim.x + threadIdx.x;
    if (t >= T_TOK) return;
    float v[NEXP];
    float mx = -1e30f;
    for (int e = 0; e < NEXP; e++) { v[e] = logits[t * NEXP + e]; mx = fmaxf(mx, v[e]); }
    for (int e = 0; e < NEXP; e++) v[e] = expf(v[e] - mx);
    int idx[TOPK]; float w8[TOPK]; float tw = 0.f;
    for (int j = 0; j < TOPK; j++) {
        int am = 0; float bm = -1.f;
        for (int e = 0; e < NEXP; e++) if (v[e] > bm) { bm = v[e]; am = e; }
        idx[j] = am; w8[j] = bm; tw += bm; v[am] = -2.f;
    }
    for (int j = 0; j < TOPK; j++) {
        int e = idx[j];
        int p = atomicAdd(&counts[e], 1);
        toks[e * T_TOK + p] = t;
        wts[e * T_TOK + p] = w8[j] / tw;
    }
}

// ---------------- flash attention (causal, GQA 16q/4kv, HD=64) ----------------
// QK: float4 over head-dim. PV: V stored transposed in smem, float4 over kv index.
__global__ void __launch_bounds__(256) attn_kernel(const float* __restrict__ qkv,
                                                   float* __restrict__ out) {
    const int qt = blockIdx.x, h = blockIdx.y, b = blockIdx.z;
    const int q0 = qt * 32;
    const int kvh = h >> 2;
    __shared__ float Qs[32][68];
    __shared__ float KVs[64][68];   // K row-major, then reused as V^T [d][kvrow]
    __shared__ float Ss[32][68];
    const int tid = threadIdx.x;
    const int r = tid >> 3;     // q row 0..31
    const int cth = tid & 7;    // col lane 0..7
    for (int i = tid; i < 32 * 64; i += 256) {
        int rr = i >> 6, d = i & 63;
        Qs[rr][d] = qkv[(size_t)(b * SSEQ + q0 + rr) * 1536 + h * 64 + d];
    }
    float m = -1e30f, l = 0.f;
    float oa[8];
    #pragma unroll
    for (int i = 0; i < 8; i++) oa[i] = 0.f;
    const int qg = q0 + r;
    const int ntiles = q0 / 64 + 1;
    for (int tkv = 0; tkv < ntiles; tkv++) {
        const int kb = tkv * 64;
        // K tile row-major
        for (int i = tid; i < 64 * 64; i += 256) {
            int rr = i >> 6, d = i & 63;
            KVs[rr][d] = qkv[(size_t)(b * SSEQ + kb + rr) * 1536 + 1024 + kvh * 64 + d];
        }
        __syncthreads();
        float sv[8];
        #pragma unroll
        for (int ci = 0; ci < 8; ci++) sv[ci] = 0.f;
        #pragma unroll
        for (int d4 = 0; d4 < 16; d4++) {
            float4 qv = *(const float4*)&Qs[r][d4 * 4];
            #pragma unroll
            for (int ci = 0; ci < 8; ci++) {
                int c = cth + ci * 8;
                float4 kv = *(const float4*)&KVs[c][d4 * 4];
                sv[ci] += qv.x * kv.x + qv.y * kv.y + qv.z * kv.z + qv.w * kv.w;
            }
        }
        #pragma unroll
        for (int ci = 0; ci < 8; ci++) {
            int c = cth + ci * 8;
            sv[ci] = (kb + c <= qg) ? sv[ci] * 0.125f : -1e30f;
        }
        float tmax = sv[0];
        #pragma unroll
        for (int ci = 1; ci < 8; ci++) tmax = fmaxf(tmax, sv[ci]);
        #pragma unroll
        for (int o = 4; o; o >>= 1) tmax = fmaxf(tmax, __shfl_xor_sync(0xffffffffu, tmax, o, 8));
        float newm = fmaxf(m, tmax);
        float corr = expf(m - newm);
        float ls = 0.f;
        #pragma unroll
        for (int ci = 0; ci < 8; ci++) {
            float p = expf(sv[ci] - newm);
            Ss[r][cth + ci * 8] = p;
            ls += p;
        }
        #pragma unroll
        for (int o = 4; o; o >>= 1) ls += __shfl_xor_sync(0xffffffffu, ls, o, 8);
        l = l * corr + ls;
        #pragma unroll
        for (int i = 0; i < 8; i++) oa[i] *= corr;
        m = newm;
        __syncthreads();
        // V tile TRANSPOSED: KVs[d][kvrow] = V[kvrow][d]
        for (int i = tid; i < 64 * 64; i += 256) {
            int rr = i >> 6, d = i & 63;
            KVs[d][rr] = qkv[(size_t)(b * SSEQ + kb + rr) * 1536 + 1280 + kvh * 64 + d];
        }
        __syncthreads();
        #pragma unroll
        for (int k4 = 0; k4 < 16; k4++) {
            float4 ps = *(const float4*)&Ss[r][k4 * 4];
            #pragma unroll
            for (int i = 0; i < 8; i++) {
                int c = cth + i * 8;      // output head-dim owned by this thread
                float4 vv = *(const float4*)&KVs[c][k4 * 4];
                oa[i] += ps.x * vv.x + ps.y * vv.y + ps.z * vv.z + ps.w * vv.w;
            }
        }
        __syncthreads();
    }
    float inv = 1.f / l;
    // pre-round: this buffer is A of the o-proj tensor-core GEMM
    #pragma unroll
    for (int i = 0; i < 8; i++)
        out[(size_t)(b * SSEQ + q0 + r) * 1024 + h * 64 + cth + i * 8] = roundtf(oa[i] * inv);
}

// ---------------- launch ----------------
extern "C" void kernel_launch(void* const* d_in, const int* in_sizes, int n_in,
                              void* d_out, int out_size) {
    const float* hid    = (const float*)d_in[0];
    const float* ln1    = (const float*)d_in[1];
    const float* ln2    = (const float*)d_in[2];
    const float* q_w    = (const float*)d_in[3];
    const float* q_b    = (const float*)d_in[4];
    const float* k_w    = (const float*)d_in[5];
    const float* k_b    = (const float*)d_in[6];
    const float* v_w    = (const float*)d_in[7];
    const float* v_b    = (const float*)d_in[8];
    const float* o_w    = (const float*)d_in[9];
    const float* gate_w = (const float*)d_in[10];
    const float* w_gate = (const float*)d_in[11];
    const float* w_up   = (const float*)d_in[12];
    const float* w_down = (const float*)d_in[13];
    const float* s_gate = (const float*)d_in[14];
    const float* s_up   = (const float*)d_in[15];
    const float* s_down = (const float*)d_in[16];
    const float* shg    = (const float*)d_in[17];
    float* out = (float*)d_out;

    void* pa = nullptr; cudaGetSymbolAddress(&pa, g_arena);
    void* pi = nullptr; cudaGetSymbolAddress(&pi, g_iarena);
    float* F = (float*)pa;
    int* toks = (int*)pi;
    int* counts = toks + NEXP * T_TOK;

    float* x     = F + OFF_X;
    float* qkv   = F + OFF_QKV;
    float* attn  = F + OFF_ATTN;
    float* h     = F + OFF_H;
    float* y     = F + OFF_Y;
    float* moe   = F + OFF_MOE;
    float* sint  = F + OFF_SINT;
    float* logit = F + OFF_LOG;
    float* g     = F + OFF_G;
    float* wts   = F + OFF_WTS;
    float* inter = F + OFF_INT;

    zero_counts_kernel<<<1, 64>>>(counts);

    // ---- attention block ----
    rmsnorm_kernel<<<T_TOK, 256>>>(hid, ln1, x);
    // fused QKV: N=1536 packed, per-column-range weight select
    mma_kernel<1, 0, 0, 1><<<dim3(12, 16, 1), 512>>>(
        x, HDIM, 0, q_w, HDIM, 0, k_w, v_w, q_b, k_b, v_b,
        nullptr, 0, nullptr, nullptr, nullptr, nullptr,
        qkv, 1536, 0, T_TOK, 1536, HDIM);
    rope_kernel<<<T_TOK, 256>>>(qkv);
    attn_kernel<<<dim3(SSEQ / 32, NHQ, BB), 256>>>(qkv, attn);
    // o-proj + residual
    mma_kernel<1, 0, 0, 0><<<dim3(8, 16, 1), 512>>>(
        attn, HDIM, 0, o_w, HDIM, 0, nullptr, nullptr, nullptr, nullptr, nullptr,
        hid, HDIM, nullptr, nullptr, nullptr, nullptr,
        h, HDIM, 0, T_TOK, 1024, HDIM);

    // ---- MoE block ----
    rmsnorm_kernel<<<T_TOK, 256>>>(h, ln2, y);
    gemm_nt_kernel<<<dim3(1, 16), 256>>>(y, HDIM, gate_w, HDIM, logit, NEXP,
                                         T_TOK, NEXP, HDIM);
    router_kernel<<<T_TOK / 256, 256>>>(logit, counts, toks, wts);

    // shared expert: gate -> sint, up fused silu*mul -> sint
    mma_kernel<1, 0, 0, 0><<<dim3(11, 16, 1), 512>>>(
        y, HDIM, 0, s_gate, HDIM, 0, nullptr, nullptr, nullptr, nullptr, nullptr,
        nullptr, 0, nullptr, nullptr, nullptr, nullptr,
        sint, IS, 0, T_TOK, IS, HDIM);
    mma_kernel<1, 0, 1, 0><<<dim3(11, 16, 1), 512>>>(
        y, HDIM, 0, s_up, HDIM, 0, nullptr, nullptr, nullptr, nullptr, nullptr,
        nullptr, 0, nullptr, nullptr, nullptr, nullptr,
        sint, IS, 0, T_TOK, IS, HDIM);
    sgate_kernel<<<T_TOK, 256>>>(y, shg, g);
    // shared down * sigmoid-gate -> moe (writes all of moe)
    mma_kernel<1, 0, 0, 0><<<dim3(8, 16, 1), 512>>>(
        sint, IS, 0, s_down, IS, 0, nullptr, nullptr, nullptr, nullptr, nullptr,
        nullptr, 0, g, nullptr, nullptr, nullptr,
        moe, HDIM, 0, T_TOK, 1024, IS);

    // routed experts: gate -> inter, up fused silu*mul -> inter, down scatter -> moe
    mma_kernel<0, 1, 0, 0><<<dim3(4, 16, NEXP), 512>>>(
        y, HDIM, 0, w_gate, IE, (size_t)HDIM * IE, nullptr, nullptr,
        nullptr, nullptr, nullptr, nullptr, 0, nullptr,
        toks, counts, nullptr, inter, IE, (size_t)T_TOK * IE, T_TOK, IE, HDIM);
    mma_kernel<0, 1, 1, 0><<<dim3(4, 16, NEXP), 512>>>(
        y, HDIM, 0, w_up, IE, (size_t)HDIM * IE, nullptr, nullptr,
        nullptr, nullptr, nullptr, nullptr, 0, nullptr,
        toks, counts, nullptr, inter, IE, (size_t)T_TOK * IE, T_TOK, IE, HDIM);
    mma_kernel<0, 2, 2, 0><<<dim3(8, 16, NEXP), 512>>>(
        inter, IE, (size_t)T_TOK * IE, w_down, HDIM, (size_t)IE * HDIM, nullptr, nullptr,
        nullptr, nullptr, nullptr, nullptr, 0, nullptr,
        toks, counts, wts, moe, HDIM, 0, T_TOK, 1024, IE);

    // final residual
    add_kernel<<<2048, 256>>>(h, moe, out, T_TOK * HDIM);
}

// round 10
// speedup vs baseline: 1.1787x; 1.1787x over previous
#include <cuda_runtime.h>
#include <math.h>
#include <stdint.h>

// ---------------- problem constants ----------------
#define T_TOK 2048      // B*S
#define HDIM  1024
#define SSEQ  1024
#define BB    2
#define NHQ   16
#define NKVH  4
#define NEXP  64
#define TOPK  8
#define IE    512
#define IS    1408

// ---------------- scratch arena (static, no allocs) ----------------
static const size_t OFF_X    = 0;          // [T,1024]
static const size_t OFF_QKV  = 2097152;    // [T,1536]  q|k|v packed
static const size_t OFF_ATTN = 5242880;    // [T,1024]
static const size_t OFF_H    = 7340032;    // [T,1024]
static const size_t OFF_Y    = 9437184;    // [T,1024]
static const size_t OFF_MOE  = 11534336;   // [T,1024]
static const size_t OFF_SINT = 13631488;   // [T,1408]
static const size_t OFF_LOG  = 16515072;   // [T,64]
static const size_t OFF_G    = 16646144;   // [T]
static const size_t OFF_WTS  = 16648192;   // [E,2048]
static const size_t OFF_INT  = 16779264;   // [E,2048,512]
__device__ float g_arena[83888128];
__device__ int   g_iarena[131136];         // toks [E,2048] then counts[64]

// ---------------- helpers ----------------
__device__ __forceinline__ float block_sum_256(float v) {
    __shared__ float red[8];
    #pragma unroll
    for (int o = 16; o; o >>= 1) v += __shfl_xor_sync(0xffffffffu, v, o);
    if ((threadIdx.x & 31) == 0) red[threadIdx.x >> 5] = v;
    __syncthreads();
    if (threadIdx.x == 0) {
        float s = 0.f;
        #pragma unroll
        for (int i = 0; i < 8; i++) s += red[i];
        red[0] = s;
    }
    __syncthreads();
    return red[0];
}

__device__ __forceinline__ uint32_t f2tf32(float f) {
    uint32_t u;
    asm("cvt.rna.tf32.f32 %0, %1;" : "=r"(u) : "f"(f));
    return u;
}
__device__ __forceinline__ float roundtf(float f) { return __uint_as_float(f2tf32(f)); }

#define MMA_TF32(d, a, b)                                                      \
    asm volatile("mma.sync.aligned.m16n8k8.row.col.f32.tf32.tf32.f32 "         \
                 "{%0,%1,%2,%3}, {%4,%5,%6,%7}, {%8,%9}, {%0,%1,%2,%3};"       \
                 : "+f"(d[0]), "+f"(d[1]), "+f"(d[2]), "+f"(d[3])              \
                 : "r"(a[0]), "r"(a[1]), "r"(a[2]), "r"(a[3]),                 \
                   "r"(b[0]), "r"(b[1]))

__device__ __forceinline__ void cpasync16(uint32_t dst, const float* src, int sz) {
    asm volatile("cp.async.cg.shared.global [%0], [%1], 16, %2;"
                 :: "r"(dst), "l"(src), "r"(sz));
}
#define CP_COMMIT() asm volatile("cp.async.commit_group;")
#define CP_WAIT0()  asm volatile("cp.async.wait_group 0;")
#define CP_WAIT1()  asm volatile("cp.async.wait_group 1;")

// ---------------- elementwise / norm kernels ----------------
__global__ void zero_counts_kernel(int* counts) { counts[threadIdx.x] = 0; }

__global__ void rmsnorm_kernel(const float* __restrict__ x, const float* __restrict__ w,
                               float* __restrict__ out) {
    int t = blockIdx.x;
    const float* xr = x + (size_t)t * HDIM;
    float s = 0.f;
    for (int i = threadIdx.x; i < HDIM; i += 256) { float v = xr[i]; s += v * v; }
    s = block_sum_256(s);
    float inv = rsqrtf(s * (1.0f / HDIM) + 1e-6f);
    float* orow = out + (size_t)t * HDIM;
    // pre-round to tf32 grid: this buffer feeds tensor-core GEMMs as A
    for (int i = threadIdx.x; i < HDIM; i += 256) orow[i] = roundtf(xr[i] * inv * w[i]);
}

__global__ void sgate_kernel(const float* __restrict__ y, const float* __restrict__ shw,
                             float* __restrict__ g) {
    int t = blockIdx.x;
    const float* yr = y + (size_t)t * HDIM;
    float s = 0.f;
    for (int i = threadIdx.x; i < HDIM; i += 256) s += yr[i] * shw[i];
    s = block_sum_256(s);
    if (threadIdx.x == 0) g[t] = 1.0f / (1.0f + expf(-s));
}

__global__ void rope_kernel(float* __restrict__ qkv) {
    __shared__ float cs[32], sn[32];
    int t = blockIdx.x;
    int s = t & (SSEQ - 1);
    if (threadIdx.x < 32) {
        double inv = exp(-(double)threadIdx.x / 32.0 * log(1000000.0));
        double ang = (double)s * inv;
        cs[threadIdx.x] = (float)cos(ang);
        sn[threadIdx.x] = (float)sin(ang);
    }
    __syncthreads();
    float* base = qkv + (size_t)t * 1536;
    for (int w = threadIdx.x; w < 20 * 32; w += blockDim.x) {
        int hh = w >> 5, i = w & 31;
        float* p = base + (hh < 16 ? hh * 64 : 1024 + (hh - 16) * 64);
        float x1 = p[i], x2 = p[i + 32];
        float c = cs[i], s2 = sn[i];
        p[i]      = x1 * c - x2 * s2;
        p[i + 32] = x2 * c + x1 * s2;
    }
}

__global__ void add_kernel(const float* __restrict__ a, const float* __restrict__ b,
                           float* __restrict__ o, int n) {
    for (int i = blockIdx.x * blockDim.x + threadIdx.x; i < n; i += gridDim.x * blockDim.x)
        o[i] = a[i] + b[i];
}

// ---------------- SIMT NT GEMM (router logits only, N=64) ----------------
__global__ void __launch_bounds__(256) gemm_nt_kernel(
    const float* __restrict__ A, int lda,
    const float* __restrict__ B, int ldb,
    float* __restrict__ C, int ldc,
    int M, int N, int K)
{
    __shared__ float As[16][128];
    __shared__ float Bs[16][64];
    const int mb = blockIdx.y * 128;
    const int nb = blockIdx.x * 64;
    const int tid = threadIdx.x;
    const int tm = (tid >> 4) * 8;
    const int tn = (tid & 15) * 4;
    float acc[8][4];
    #pragma unroll
    for (int i = 0; i < 8; i++)
        #pragma unroll
        for (int j = 0; j < 4; j++) acc[i][j] = 0.f;

    for (int kb = 0; kb < K; kb += 16) {
        #pragma unroll
        for (int i = 0; i < 2; i++) {
            int f4 = tid + i * 256;
            int m = f4 >> 2, k4 = (f4 & 3) << 2;
            float4 v = make_float4(0.f, 0.f, 0.f, 0.f);
            int gm = mb + m;
            if (gm < M) v = *(const float4*)(A + (size_t)gm * lda + kb + k4);
            As[k4][m] = v.x; As[k4 + 1][m] = v.y; As[k4 + 2][m] = v.z; As[k4 + 3][m] = v.w;
        }
        {
            int n = tid >> 2, k4 = (tid & 3) << 2;
            int gn = nb + n;
            float4 v = make_float4(0.f, 0.f, 0.f, 0.f);
            if (gn < N) v = *(const float4*)(B + (size_t)gn * ldb + kb + k4);
            Bs[k4][n] = v.x; Bs[k4 + 1][n] = v.y; Bs[k4 + 2][n] = v.z; Bs[k4 + 3][n] = v.w;
        }
        __syncthreads();
        #pragma unroll
        for (int k = 0; k < 16; k++) {
            float4 a0 = *(const float4*)&As[k][tm];
            float4 a1 = *(const float4*)&As[k][tm + 4];
            float4 b  = *(const float4*)&Bs[k][tn];
            float av[8] = {a0.x, a0.y, a0.z, a0.w, a1.x, a1.y, a1.z, a1.w};
            float bv[4] = {b.x, b.y, b.z, b.w};
            #pragma unroll
            for (int i = 0; i < 8; i++)
                #pragma unroll
                for (int j = 0; j < 4; j++) acc[i][j] += av[i] * bv[j];
        }
        __syncthreads();
    }
    #pragma unroll
    for (int i = 0; i < 8; i++) {
        int gm = mb + tm + i;
        if (gm >= M) break;
        #pragma unroll
        for (int j = 0; j < 4; j++) {
            int gn = nb + tn + j;
            if (gn < N) C[(size_t)gm * ldc + gn] = acc[i][j];
        }
    }
}

// ---------------- tf32 tensor-core GEMM, 128x128 block, 256 thr, 3-stage cp.async ----------------
// BN: 0 = B is [K,N] n-contiguous (NN), 1 = B is [N,K] k-contiguous (NT)
// AMODE: 0 = plain A rows, 1 = gather via toks, 2 = expert slot rows
// EPI: 0 = C = res + scale*(acc+bias); 1 = C = tf32(silu(C)*acc); 2 = atomicAdd(moe, w*acc)
// QKV: 1 = select B/bias by output-column range (q|k|v packed, N=1536)
// A must be pre-rounded to tf32; B is cvt.rna'd on fragment load.
#define KC     16
#define APAD   20      // row stride (words) for k-contiguous tiles
#define ASTAGE 2560    // 128*20 words per stage
#define BPADN  136     // row stride for NN [16][136]

template<int BN, int AMODE, int EPI, int QKV>
__global__ void __launch_bounds__(256) mma_kernel(
    const float* __restrict__ A, int lda, size_t strideAe,
    const float* __restrict__ B, int ldb, size_t strideBe,
    const float* __restrict__ B2, const float* __restrict__ B3,
    const float* __restrict__ bias, const float* __restrict__ bias2,
    const float* __restrict__ bias3,
    const float* __restrict__ res, int ldres,
    const float* __restrict__ scale,
    const int* __restrict__ toks, const int* __restrict__ counts,
    const float* __restrict__ wts,
    float* __restrict__ C, int ldc, size_t strideCe,
    int M, int N, int K)
{
    const int e = blockIdx.z;
    int bound = M;
    if (AMODE != 0) bound = counts[e];
    const int mb = blockIdx.y * 128;
    if (mb >= bound) return;
    const int nb = blockIdx.x * 128;
    if (AMODE == 2) A += (size_t)e * strideAe;
    B += (size_t)e * strideBe;
    C += (size_t)e * strideCe;

    // QKV column-range weight select
    const float* Bw = B;
    const float* bi = bias;
    int rowoff = 0;
    if (QKV) {
        if (nb >= 1280)      { Bw = B3; bi = bias3; rowoff = 1280; }
        else if (nb >= 1024) { Bw = B2; bi = bias2; rowoff = 1024; }
    }

    __shared__ float As[3][ASTAGE];
    __shared__ float Bs[3][ASTAGE];

    const int tid = threadIdx.x;
    const int wid = tid >> 5, lane = tid & 31;
    const int g = lane >> 2, tg = lane & 3;
    const int wm = (wid & 1) * 64, wn = (wid >> 1) * 32;

    const uint32_t smA = (uint32_t)__cvta_generic_to_shared(&As[0][0]);
    const uint32_t smB = (uint32_t)__cvta_generic_to_shared(&Bs[0][0]);

    // ---- per-thread cp.async descriptors: 2 A chunks + 2 B chunks ----
    const float* asrc[2]; int asz[2]; uint32_t adst[2];
    #pragma unroll
    for (int i = 0; i < 2; i++) {
        int id = tid + i * 256;           // 0..511
        int m = id >> 2, kq = id & 3;
        int gm = mb + m;
        bool valid = gm < bound;
        int row = valid ? gm : 0;
        if (AMODE == 1) row = valid ? toks[e * T_TOK + gm] : 0;
        asrc[i] = A + (size_t)row * lda + kq * 4;
        asz[i] = valid ? 16 : 0;
        adst[i] = smA + (uint32_t)(m * APAD + kq * 4) * 4u;
    }
    const float* bsrc[2]; uint32_t bdst[2];
    long bstep;                            // floats to advance per iteration
    #pragma unroll
    for (int i = 0; i < 2; i++) {
        int id = tid + i * 256;
        if (BN == 1) {
            int n = id >> 2, kq = id & 3;
            bsrc[i] = Bw + (size_t)(nb + n - rowoff) * ldb + kq * 4;
            bdst[i] = smB + (uint32_t)(n * APAD + kq * 4) * 4u;
        } else {
            int kk = id >> 5, n4 = (id & 31) << 2;
            bsrc[i] = B + (size_t)kk * ldb + nb + n4;
            bdst[i] = smB + (uint32_t)(kk * BPADN + n4) * 4u;
        }
    }
    bstep = (BN == 1) ? KC : (long)KC * ldb;

    float acc[4][4][4];
    #pragma unroll
    for (int mt = 0; mt < 4; mt++)
        #pragma unroll
        for (int nt = 0; nt < 4; nt++)
            #pragma unroll
            for (int q = 0; q < 4; q++) acc[mt][nt][q] = 0.f;

    const int niter = K / KC;

    // prologue: stages 0 and 1
    #pragma unroll
    for (int st = 0; st < 2; st++) {
        uint32_t soff = (uint32_t)(st * ASTAGE * 4);
        #pragma unroll
        for (int i = 0; i < 2; i++) cpasync16(adst[i] + soff, asrc[i], asz[i]);
        #pragma unroll
        for (int i = 0; i < 2; i++) cpasync16(bdst[i] + soff, bsrc[i], 16);
        CP_COMMIT();
        #pragma unroll
        for (int i = 0; i < 2; i++) { asrc[i] += KC; bsrc[i] += bstep; }
    }

    for (int it = 0; it < niter; it++) {
        const int s = it % 3;
        if (it + 1 < niter) CP_WAIT1(); else CP_WAIT0();
        __syncthreads();
        if (it + 2 < niter) {
            const uint32_t soff = (uint32_t)(((it + 2) % 3) * ASTAGE * 4);
            #pragma unroll
            for (int i = 0; i < 2; i++) cpasync16(adst[i] + soff, asrc[i], asz[i]);
            #pragma unroll
            for (int i = 0; i < 2; i++) cpasync16(bdst[i] + soff, bsrc[i], 16);
            CP_COMMIT();
            #pragma unroll
            for (int i = 0; i < 2; i++) { asrc[i] += KC; bsrc[i] += bstep; }
        }
        // compute 2 k-steps of 8
        #pragma unroll
        for (int ks = 0; ks < KC; ks += 8) {
            uint32_t af[4][4], bf[4][2];
            #pragma unroll
            for (int mt = 0; mt < 4; mt++) {
                int r = wm + mt * 16 + g;
                af[mt][0] = __float_as_uint(As[s][r * APAD + ks + tg]);
                af[mt][1] = __float_as_uint(As[s][(r + 8) * APAD + ks + tg]);
                af[mt][2] = __float_as_uint(As[s][r * APAD + ks + tg + 4]);
                af[mt][3] = __float_as_uint(As[s][(r + 8) * APAD + ks + tg + 4]);
            }
            #pragma unroll
            for (int nt = 0; nt < 4; nt++) {
                int c = wn + nt * 8 + g;
                if (BN == 1) {
                    bf[nt][0] = f2tf32(Bs[s][c * APAD + ks + tg]);
                    bf[nt][1] = f2tf32(Bs[s][c * APAD + ks + tg + 4]);
                } else {
                    bf[nt][0] = f2tf32(Bs[s][(ks + tg) * BPADN + c]);
                    bf[nt][1] = f2tf32(Bs[s][(ks + tg + 4) * BPADN + c]);
                }
            }
            #pragma unroll
            for (int mt = 0; mt < 4; mt++)
                #pragma unroll
                for (int nt = 0; nt < 4; nt++)
                    MMA_TF32(acc[mt][nt], af[mt], bf[nt]);
        }
        __syncthreads();
    }

    // ---- epilogue ----
    #pragma unroll
    for (int mt = 0; mt < 4; mt++) {
        int rbase = mb + wm + mt * 16 + g;
        #pragma unroll
        for (int half = 0; half < 2; half++) {
            int rr = rbase + half * 8;
            if (rr >= bound) continue;
            if (EPI == 2) {
                int t = toks[e * T_TOK + rr];
                float w = wts[e * T_TOK + rr];
                float* mp = C + (size_t)t * ldc;
                #pragma unroll
                for (int nt = 0; nt < 4; nt++) {
                    int c = nb + wn + nt * 8 + 2 * tg;
                    atomicAdd(&mp[c],     w * acc[mt][nt][half * 2 + 0]);
                    atomicAdd(&mp[c + 1], w * acc[mt][nt][half * 2 + 1]);
                }
            } else if (EPI == 1) {
                float* cp = C + (size_t)rr * ldc;
                #pragma unroll
                for (int nt = 0; nt < 4; nt++) {
                    int c = nb + wn + nt * 8 + 2 * tg;
                    float2 p = *(float2*)&cp[c];
                    float v0 = p.x / (1.0f + expf(-p.x)) * acc[mt][nt][half * 2 + 0];
                    float v1 = p.y / (1.0f + expf(-p.y)) * acc[mt][nt][half * 2 + 1];
                    *(float2*)&cp[c] = make_float2(roundtf(v0), roundtf(v1));
                }
            } else {
                float sc = scale ? scale[rr] : 1.f;
                float* cp = C + (size_t)rr * ldc;
                const float* rp = res ? res + (size_t)rr * ldres : nullptr;
                #pragma unroll
                for (int nt = 0; nt < 4; nt++) {
                    int c = nb + wn + nt * 8 + 2 * tg;
                    float v0 = acc[mt][nt][half * 2 + 0];
                    float v1 = acc[mt][nt][half * 2 + 1];
                    if (bi) { v0 += bi[c - rowoff]; v1 += bi[c + 1 - rowoff]; }
                    v0 *= sc; v1 *= sc;
                    if (rp) { v0 += rp[c]; v1 += rp[c + 1]; }
                    *(float2*)&cp[c] = make_float2(v0, v1);
                }
            }
        }
    }
}

// ---------------- router top-k ----------------
__global__ void router_kernel(const float* __restrict__ logits, int* __restrict__ counts,
                              int* __restrict__ toks, float* __restrict__ wts) {
    int t = blockIdx.x * blockDim.x + threadIdx.x;
    if (t >= T_TOK) return;
    float v[NEXP];
    float mx = -1e30f;
    for (int e = 0; e < NEXP; e++) { v[e] = logits[t * NEXP + e]; mx = fmaxf(mx, v[e]); }
    for (int e = 0; e < NEXP; e++) v[e] = expf(v[e] - mx);
    int idx[TOPK]; float w8[TOPK]; float tw = 0.f;
    for (int j = 0; j < TOPK; j++) {
        int am = 0; float bm = -1.f;
        for (int e = 0; e < NEXP; e++) if (v[e] > bm) { bm = v[e]; am = e; }
        idx[j] = am; w8[j] = bm; tw += bm; v[am] = -2.f;
    }
    for (int j = 0; j < TOPK; j++) {
        int e = idx[j];
        int p = atomicAdd(&counts[e], 1);
        toks[e * T_TOK + p] = t;
        wts[e * T_TOK + p] = w8[j] / tw;
    }
}

// ---------------- flash attention (causal, GQA 16q/4kv, HD=64) ----------------
// QK: float4 over head-dim. PV: V stored transposed in smem, float4 over kv index.
__global__ void __launch_bounds__(256) attn_kernel(const float* __restrict__ qkv,
                                                   float* __restrict__ out) {
    const int qt = blockIdx.x, h = blockIdx.y, b = blockIdx.z;
    const int q0 = qt * 32;
    const int kvh = h >> 2;
    __shared__ float Qs[32][68];
    __shared__ float KVs[64][68];   // K row-major, then reused as V^T [d][kvrow]
    __shared__ float Ss[32][68];
    const int tid = threadIdx.x;
    const int r = tid >> 3;     // q row 0..31
    const int cth = tid & 7;    // col lane 0..7
    for (int i = tid; i < 32 * 64; i += 256) {
        int rr = i >> 6, d = i & 63;
        Qs[rr][d] = qkv[(size_t)(b * SSEQ + q0 + rr) * 1536 + h * 64 + d];
    }
    float m = -1e30f, l = 0.f;
    float oa[8];
    #pragma unroll
    for (int i = 0; i < 8; i++) oa[i] = 0.f;
    const int qg = q0 + r;
    const int ntiles = q0 / 64 + 1;
    for (int tkv = 0; tkv < ntiles; tkv++) {
        const int kb = tkv * 64;
        // K tile row-major
        for (int i = tid; i < 64 * 64; i += 256) {
            int rr = i >> 6, d = i & 63;
            KVs[rr][d] = qkv[(size_t)(b * SSEQ + kb + rr) * 1536 + 1024 + kvh * 64 + d];
        }
        __syncthreads();
        float sv[8];
        #pragma unroll
        for (int ci = 0; ci < 8; ci++) sv[ci] = 0.f;
        #pragma unroll
        for (int d4 = 0; d4 < 16; d4++) {
            float4 qv = *(const float4*)&Qs[r][d4 * 4];
            #pragma unroll
            for (int ci = 0; ci < 8; ci++) {
                int c = cth + ci * 8;
                float4 kv = *(const float4*)&KVs[c][d4 * 4];
                sv[ci] += qv.x * kv.x + qv.y * kv.y + qv.z * kv.z + qv.w * kv.w;
            }
        }
        #pragma unroll
        for (int ci = 0; ci < 8; ci++) {
            int c = cth + ci * 8;
            sv[ci] = (kb + c <= qg) ? sv[ci] * 0.125f : -1e30f;
        }
        float tmax = sv[0];
        #pragma unroll
        for (int ci = 1; ci < 8; ci++) tmax = fmaxf(tmax, sv[ci]);
        #pragma unroll
        for (int o = 4; o; o >>= 1) tmax = fmaxf(tmax, __shfl_xor_sync(0xffffffffu, tmax, o, 8));
        float newm = fmaxf(m, tmax);
        float corr = expf(m - newm);
        float ls = 0.f;
        #pragma unroll
        for (int ci = 0; ci < 8; ci++) {
            float p = expf(sv[ci] - newm);
            Ss[r][cth + ci * 8] = p;
            ls += p;
        }
        #pragma unroll
        for (int o = 4; o; o >>= 1) ls += __shfl_xor_sync(0xffffffffu, ls, o, 8);
        l = l * corr + ls;
        #pragma unroll
        for (int i = 0; i < 8; i++) oa[i] *= corr;
        m = newm;
        __syncthreads();
        // V tile TRANSPOSED: KVs[d][kvrow] = V[kvrow][d]
        for (int i = tid; i < 64 * 64; i += 256) {
            int rr = i >> 6, d = i & 63;
            KVs[d][rr] = qkv[(size_t)(b * SSEQ + kb + rr) * 1536 + 1280 + kvh * 64 + d];
        }
        __syncthreads();
        #pragma unroll
        for (int k4 = 0; k4 < 16; k4++) {
            float4 ps = *(const float4*)&Ss[r][k4 * 4];
            #pragma unroll
            for (int i = 0; i < 8; i++) {
                int c = cth + i * 8;      // output head-dim owned by this thread
                float4 vv = *(const float4*)&KVs[c][k4 * 4];
                oa[i] += ps.x * vv.x + ps.y * vv.y + ps.z * vv.z + ps.w * vv.w;
            }
        }
        __syncthreads();
    }
    float inv = 1.f / l;
    // pre-round: this buffer is A of the o-proj tensor-core GEMM
    #pragma unroll
    for (int i = 0; i < 8; i++)
        out[(size_t)(b * SSEQ + q0 + r) * 1024 + h * 64 + cth + i * 8] = roundtf(oa[i] * inv);
}

// ---------------- launch ----------------
extern "C" void kernel_launch(void* const* d_in, const int* in_sizes, int n_in,
                              void* d_out, int out_size) {
    const float* hid    = (const float*)d_in[0];
    const float* ln1    = (const float*)d_in[1];
    const float* ln2    = (const float*)d_in[2];
    const float* q_w    = (const float*)d_in[3];
    const float* q_b    = (const float*)d_in[4];
    const float* k_w    = (const float*)d_in[5];
    const float* k_b    = (const float*)d_in[6];
    const float* v_w    = (const float*)d_in[7];
    const float* v_b    = (const float*)d_in[8];
    const float* o_w    = (const float*)d_in[9];
    const float* gate_w = (const float*)d_in[10];
    const float* w_gate = (const float*)d_in[11];
    const float* w_up   = (const float*)d_in[12];
    const float* w_down = (const float*)d_in[13];
    const float* s_gate = (const float*)d_in[14];
    const float* s_up   = (const float*)d_in[15];
    const float* s_down = (const float*)d_in[16];
    const float* shg    = (const float*)d_in[17];
    float* out = (float*)d_out;

    void* pa = nullptr; cudaGetSymbolAddress(&pa, g_arena);
    void* pi = nullptr; cudaGetSymbolAddress(&pi, g_iarena);
    float* F = (float*)pa;
    int* toks = (int*)pi;
    int* counts = toks + NEXP * T_TOK;

    float* x     = F + OFF_X;
    float* qkv   = F + OFF_QKV;
    float* attn  = F + OFF_ATTN;
    float* h     = F + OFF_H;
    float* y     = F + OFF_Y;
    float* moe   = F + OFF_MOE;
    float* sint  = F + OFF_SINT;
    float* logit = F + OFF_LOG;
    float* g     = F + OFF_G;
    float* wts   = F + OFF_WTS;
    float* inter = F + OFF_INT;

    zero_counts_kernel<<<1, 64>>>(counts);

    // ---- attention block ----
    rmsnorm_kernel<<<T_TOK, 256>>>(hid, ln1, x);
    // fused QKV: N=1536 packed, per-column-range weight select
    mma_kernel<1, 0, 0, 1><<<dim3(12, 16, 1), 256>>>(
        x, HDIM, 0, q_w, HDIM, 0, k_w, v_w, q_b, k_b, v_b,
        nullptr, 0, nullptr, nullptr, nullptr, nullptr,
        qkv, 1536, 0, T_TOK, 1536, HDIM);
    rope_kernel<<<T_TOK, 256>>>(qkv);
    attn_kernel<<<dim3(SSEQ / 32, NHQ, BB), 256>>>(qkv, attn);
    // o-proj + residual
    mma_kernel<1, 0, 0, 0><<<dim3(8, 16, 1), 256>>>(
        attn, HDIM, 0, o_w, HDIM, 0, nullptr, nullptr, nullptr, nullptr, nullptr,
        hid, HDIM, nullptr, nullptr, nullptr, nullptr,
        h, HDIM, 0, T_TOK, 1024, HDIM);

    // ---- MoE block ----
    rmsnorm_kernel<<<T_TOK, 256>>>(h, ln2, y);
    gemm_nt_kernel<<<dim3(1, 16), 256>>>(y, HDIM, gate_w, HDIM, logit, NEXP,
                                         T_TOK, NEXP, HDIM);
    router_kernel<<<T_TOK / 256, 256>>>(logit, counts, toks, wts);

    // shared expert: gate -> sint, up fused silu*mul -> sint
    mma_kernel<1, 0, 0, 0><<<dim3(11, 16, 1), 256>>>(
        y, HDIM, 0, s_gate, HDIM, 0, nullptr, nullptr, nullptr, nullptr, nullptr,
        nullptr, 0, nullptr, nullptr, nullptr, nullptr,
        sint, IS, 0, T_TOK, IS, HDIM);
    mma_kernel<1, 0, 1, 0><<<dim3(11, 16, 1), 256>>>(
        y, HDIM, 0, s_up, HDIM, 0, nullptr, nullptr, nullptr, nullptr, nullptr,
        nullptr, 0, nullptr, nullptr, nullptr, nullptr,
        sint, IS, 0, T_TOK, IS, HDIM);
    sgate_kernel<<<T_TOK, 256>>>(y, shg, g);
    // shared down * sigmoid-gate -> moe (writes all of moe)
    mma_kernel<1, 0, 0, 0><<<dim3(8, 16, 1), 256>>>(
        sint, IS, 0, s_down, IS, 0, nullptr, nullptr, nullptr, nullptr, nullptr,
        nullptr, 0, g, nullptr, nullptr, nullptr,
        moe, HDIM, 0, T_TOK, 1024, IS);

    // routed experts: gate -> inter, up fused silu*mul -> inter, down scatter -> moe
    mma_kernel<0, 1, 0, 0><<<dim3(4, 16, NEXP), 256>>>(
        y, HDIM, 0, w_gate, IE, (size_t)HDIM * IE, nullptr, nullptr,
        nullptr, nullptr, nullptr, nullptr, 0, nullptr,
        toks, counts, nullptr, inter, IE, (size_t)T_TOK * IE, T_TOK, IE, HDIM);
    mma_kernel<0, 1, 1, 0><<<dim3(4, 16, NEXP), 256>>>(
        y, HDIM, 0, w_up, IE, (size_t)HDIM * IE, nullptr, nullptr,
        nullptr, nullptr, nullptr, nullptr, 0, nullptr,
        toks, counts, nullptr, inter, IE, (size_t)T_TOK * IE, T_TOK, IE, HDIM);
    mma_kernel<0, 2, 2, 0><<<dim3(8, 16, NEXP), 256>>>(
        inter, IE, (size_t)T_TOK * IE, w_down, HDIM, (size_t)IE * HDIM, nullptr, nullptr,
        nullptr, nullptr, nullptr, nullptr, 0, nullptr,
        toks, counts, wts, moe, HDIM, 0, T_TOK, 1024, IE);

    // final residual
    add_kernel<<<2048, 256>>>(h, moe, out, T_TOK * HDIM);
}

// round 11
// speedup vs baseline: 1.2388x; 1.0510x over previous
#include <cuda_runtime.h>
#include <math.h>
#include <stdint.h>

// ---------------- problem constants ----------------
#define T_TOK 2048      // B*S
#define HDIM  1024
#define SSEQ  1024
#define BB    2
#define NHQ   16
#define NKVH  4
#define NEXP  64
#define TOPK  8
#define IE    512
#define IS    1408

// ---------------- scratch arena (static, no allocs) ----------------
static const size_t OFF_X    = 0;          // [T,1024]
static const size_t OFF_QKV  = 2097152;    // [T,1536]  q|k|v packed
static const size_t OFF_ATTN = 5242880;    // [T,1024]
static const size_t OFF_H    = 7340032;    // [T,1024]
static const size_t OFF_Y    = 9437184;    // [T,1024]
static const size_t OFF_MOE  = 11534336;   // [T,1024]
static const size_t OFF_SINT = 13631488;   // [T,1408]
static const size_t OFF_LOG  = 16515072;   // [T,64]
static const size_t OFF_G    = 16646144;   // [T]
static const size_t OFF_WTS  = 16648192;   // [E,2048]
static const size_t OFF_INT  = 16779264;   // [E,2048,512]
static const size_t OFF_ROPE = 83888128;   // [1024,64] cos|sin table
__device__ float g_arena[83953664];
__device__ int   g_iarena[131136];         // toks [E,2048] then counts[64]

// ---------------- helpers ----------------
__device__ __forceinline__ float block_sum_256(float v) {
    __shared__ float red[8];
    #pragma unroll
    for (int o = 16; o; o >>= 1) v += __shfl_xor_sync(0xffffffffu, v, o);
    if ((threadIdx.x & 31) == 0) red[threadIdx.x >> 5] = v;
    __syncthreads();
    if (threadIdx.x == 0) {
        float s = 0.f;
        #pragma unroll
        for (int i = 0; i < 8; i++) s += red[i];
        red[0] = s;
    }
    __syncthreads();
    return red[0];
}

__device__ __forceinline__ uint32_t f2tf32(float f) {
    uint32_t u;
    asm("cvt.rna.tf32.f32 %0, %1;" : "=r"(u) : "f"(f));
    return u;
}
__device__ __forceinline__ float roundtf(float f) { return __uint_as_float(f2tf32(f)); }

#define MMA_TF32(d, a, b)                                                      \
    asm volatile("mma.sync.aligned.m16n8k8.row.col.f32.tf32.tf32.f32 "         \
                 "{%0,%1,%2,%3}, {%4,%5,%6,%7}, {%8,%9}, {%0,%1,%2,%3};"       \
                 : "+f"(d[0]), "+f"(d[1]), "+f"(d[2]), "+f"(d[3])              \
                 : "r"(a[0]), "r"(a[1]), "r"(a[2]), "r"(a[3]),                 \
                   "r"(b[0]), "r"(b[1]))

__device__ __forceinline__ void cpasync16(uint32_t dst, const float* src, int sz) {
    asm volatile("cp.async.cg.shared.global [%0], [%1], 16, %2;"
                 :: "r"(dst), "l"(src), "r"(sz));
}
#define CP_COMMIT() asm volatile("cp.async.commit_group;")
#define CP_WAIT0()  asm volatile("cp.async.wait_group 0;")
#define CP_WAIT1()  asm volatile("cp.async.wait_group 1;")

// ---------------- elementwise / norm kernels ----------------
__global__ void zero_counts_kernel(int* counts) { counts[threadIdx.x] = 0; }

__global__ void rmsnorm_kernel(const float* __restrict__ x, const float* __restrict__ w,
                               float* __restrict__ out) {
    int t = blockIdx.x;
    const float* xr = x + (size_t)t * HDIM;
    float s = 0.f;
    for (int i = threadIdx.x; i < HDIM; i += 256) { float v = xr[i]; s += v * v; }
    s = block_sum_256(s);
    float inv = rsqrtf(s * (1.0f / HDIM) + 1e-6f);
    float* orow = out + (size_t)t * HDIM;
    // pre-round to tf32 grid: this buffer feeds tensor-core GEMMs as A
    for (int i = threadIdx.x; i < HDIM; i += 256) orow[i] = roundtf(xr[i] * inv * w[i]);
}

__global__ void sgate_kernel(const float* __restrict__ y, const float* __restrict__ shw,
                             float* __restrict__ g) {
    int t = blockIdx.x;
    const float* yr = y + (size_t)t * HDIM;
    float s = 0.f;
    for (int i = threadIdx.x; i < HDIM; i += 256) s += yr[i] * shw[i];
    s = block_sum_256(s);
    if (threadIdx.x == 0) g[t] = 1.0f / (1.0f + expf(-s));
}

__global__ void rope_table_kernel(float* __restrict__ tab) {
    int s = blockIdx.x, i = threadIdx.x;   // 1024 blocks x 32 threads
    double inv = exp(-(double)i / 32.0 * log(1000000.0));
    double ang = (double)s * inv;
    tab[s * 64 + i]      = (float)cos(ang);
    tab[s * 64 + 32 + i] = (float)sin(ang);
}

__global__ void rope_kernel(float* __restrict__ qkv, const float* __restrict__ tab) {
    __shared__ float cs[32], sn[32];
    int t = blockIdx.x;
    int s = t & (SSEQ - 1);
    if (threadIdx.x < 64) {
        float v = tab[s * 64 + threadIdx.x];
        if (threadIdx.x < 32) cs[threadIdx.x] = v; else sn[threadIdx.x - 32] = v;
    }
    __syncthreads();
    float* base = qkv + (size_t)t * 1536;
    for (int w = threadIdx.x; w < 20 * 32; w += blockDim.x) {
        int hh = w >> 5, i = w & 31;
        float* p = base + (hh < 16 ? hh * 64 : 1024 + (hh - 16) * 64);
        float x1 = p[i], x2 = p[i + 32];
        float c = cs[i], s2 = sn[i];
        p[i]      = x1 * c - x2 * s2;
        p[i + 32] = x2 * c + x1 * s2;
    }
}

__global__ void add_kernel(const float* __restrict__ a, const float* __restrict__ b,
                           float* __restrict__ o, int n) {
    for (int i = blockIdx.x * blockDim.x + threadIdx.x; i < n; i += gridDim.x * blockDim.x)
        o[i] = a[i] + b[i];
}

// ---------------- SIMT NT GEMM (router logits only, N=64) ----------------
__global__ void __launch_bounds__(256) gemm_nt_kernel(
    const float* __restrict__ A, int lda,
    const float* __restrict__ B, int ldb,
    float* __restrict__ C, int ldc,
    int M, int N, int K)
{
    __shared__ float As[16][128];
    __shared__ float Bs[16][64];
    const int mb = blockIdx.y * 128;
    const int nb = blockIdx.x * 64;
    const int tid = threadIdx.x;
    const int tm = (tid >> 4) * 8;
    const int tn = (tid & 15) * 4;
    float acc[8][4];
    #pragma unroll
    for (int i = 0; i < 8; i++)
        #pragma unroll
        for (int j = 0; j < 4; j++) acc[i][j] = 0.f;

    for (int kb = 0; kb < K; kb += 16) {
        #pragma unroll
        for (int i = 0; i < 2; i++) {
            int f4 = tid + i * 256;
            int m = f4 >> 2, k4 = (f4 & 3) << 2;
            float4 v = make_float4(0.f, 0.f, 0.f, 0.f);
            int gm = mb + m;
            if (gm < M) v = *(const float4*)(A + (size_t)gm * lda + kb + k4);
            As[k4][m] = v.x; As[k4 + 1][m] = v.y; As[k4 + 2][m] = v.z; As[k4 + 3][m] = v.w;
        }
        {
            int n = tid >> 2, k4 = (tid & 3) << 2;
            int gn = nb + n;
            float4 v = make_float4(0.f, 0.f, 0.f, 0.f);
            if (gn < N) v = *(const float4*)(B + (size_t)gn * ldb + kb + k4);
            Bs[k4][n] = v.x; Bs[k4 + 1][n] = v.y; Bs[k4 + 2][n] = v.z; Bs[k4 + 3][n] = v.w;
        }
        __syncthreads();
        #pragma unroll
        for (int k = 0; k < 16; k++) {
            float4 a0 = *(const float4*)&As[k][tm];
            float4 a1 = *(const float4*)&As[k][tm + 4];
            float4 b  = *(const float4*)&Bs[k][tn];
            float av[8] = {a0.x, a0.y, a0.z, a0.w, a1.x, a1.y, a1.z, a1.w};
            float bv[4] = {b.x, b.y, b.z, b.w};
            #pragma unroll
            for (int i = 0; i < 8; i++)
                #pragma unroll
                for (int j = 0; j < 4; j++) acc[i][j] += av[i] * bv[j];
        }
        __syncthreads();
    }
    #pragma unroll
    for (int i = 0; i < 8; i++) {
        int gm = mb + tm + i;
        if (gm >= M) break;
        #pragma unroll
        for (int j = 0; j < 4; j++) {
            int gn = nb + tn + j;
            if (gn < N) C[(size_t)gm * ldc + gn] = acc[i][j];
        }
    }
}

// ---------------- tf32 tensor-core GEMM, 128x128 block, 256 thr, 3-stage cp.async ----------------
// BN: 0 = B is [K,N] n-contiguous (NN), 1 = B is [N,K] k-contiguous (NT)
// AMODE: 0 = plain A rows, 1 = gather via toks, 2 = expert slot rows
// EPI: 0 = C = res + scale*(acc+bias); 2 = atomicAdd(moe, w*acc)
// QKV: 1 = select B/bias by output-column range (q|k|v packed, N=1536)
// A must be pre-rounded to tf32; B is cvt.rna'd on fragment load.
#define KC     16
#define APAD   20      // row stride (words) for k-contiguous tiles
#define ASTAGE 2560    // 128*20 words per stage
#define BPADN  136     // row stride for NN [16][136]

template<int BN, int AMODE, int EPI, int QKV>
__global__ void __launch_bounds__(256) mma_kernel(
    const float* __restrict__ A, int lda, size_t strideAe,
    const float* __restrict__ B, int ldb, size_t strideBe,
    const float* __restrict__ B2, const float* __restrict__ B3,
    const float* __restrict__ bias, const float* __restrict__ bias2,
    const float* __restrict__ bias3,
    const float* __restrict__ res, int ldres,
    const float* __restrict__ scale,
    const int* __restrict__ toks, const int* __restrict__ counts,
    const float* __restrict__ wts,
    float* __restrict__ C, int ldc, size_t strideCe,
    int M, int N, int K)
{
    const int e = blockIdx.z;
    int bound = M;
    if (AMODE != 0) bound = counts[e];
    const int mb = blockIdx.y * 128;
    if (mb >= bound) return;
    const int nb = blockIdx.x * 128;
    if (AMODE == 2) A += (size_t)e * strideAe;
    B += (size_t)e * strideBe;
    C += (size_t)e * strideCe;

    // QKV column-range weight select
    const float* Bw = B;
    const float* bi = bias;
    int rowoff = 0;
    if (QKV) {
        if (nb >= 1280)      { Bw = B3; bi = bias3; rowoff = 1280; }
        else if (nb >= 1024) { Bw = B2; bi = bias2; rowoff = 1024; }
    }

    __shared__ float As[3][ASTAGE];
    __shared__ float Bs[3][ASTAGE];

    const int tid = threadIdx.x;
    const int wid = tid >> 5, lane = tid & 31;
    const int g = lane >> 2, tg = lane & 3;
    const int wm = (wid & 1) * 64, wn = (wid >> 1) * 32;

    const uint32_t smA = (uint32_t)__cvta_generic_to_shared(&As[0][0]);
    const uint32_t smB = (uint32_t)__cvta_generic_to_shared(&Bs[0][0]);

    // ---- per-thread cp.async descriptors: 2 A chunks + 2 B chunks ----
    const float* asrc[2]; int asz[2]; uint32_t adst[2];
    #pragma unroll
    for (int i = 0; i < 2; i++) {
        int id = tid + i * 256;           // 0..511
        int m = id >> 2, kq = id & 3;
        int gm = mb + m;
        bool valid = gm < bound;
        int row = valid ? gm : 0;
        if (AMODE == 1) row = valid ? toks[e * T_TOK + gm] : 0;
        asrc[i] = A + (size_t)row * lda + kq * 4;
        asz[i] = valid ? 16 : 0;
        adst[i] = smA + (uint32_t)(m * APAD + kq * 4) * 4u;
    }
    const float* bsrc[2]; uint32_t bdst[2];
    long bstep;                            // floats to advance per iteration
    #pragma unroll
    for (int i = 0; i < 2; i++) {
        int id = tid + i * 256;
        if (BN == 1) {
            int n = id >> 2, kq = id & 3;
            bsrc[i] = Bw + (size_t)(nb + n - rowoff) * ldb + kq * 4;
            bdst[i] = smB + (uint32_t)(n * APAD + kq * 4) * 4u;
        } else {
            int kk = id >> 5, n4 = (id & 31) << 2;
            bsrc[i] = B + (size_t)kk * ldb + nb + n4;
            bdst[i] = smB + (uint32_t)(kk * BPADN + n4) * 4u;
        }
    }
    bstep = (BN == 1) ? KC : (long)KC * ldb;

    float acc[4][4][4];
    #pragma unroll
    for (int mt = 0; mt < 4; mt++)
        #pragma unroll
        for (int nt = 0; nt < 4; nt++)
            #pragma unroll
            for (int q = 0; q < 4; q++) acc[mt][nt][q] = 0.f;

    const int niter = K / KC;

    // prologue: stages 0 and 1
    #pragma unroll
    for (int st = 0; st < 2; st++) {
        uint32_t soff = (uint32_t)(st * ASTAGE * 4);
        #pragma unroll
        for (int i = 0; i < 2; i++) cpasync16(adst[i] + soff, asrc[i], asz[i]);
        #pragma unroll
        for (int i = 0; i < 2; i++) cpasync16(bdst[i] + soff, bsrc[i], 16);
        CP_COMMIT();
        #pragma unroll
        for (int i = 0; i < 2; i++) { asrc[i] += KC; bsrc[i] += bstep; }
    }

    for (int it = 0; it < niter; it++) {
        const int s = it % 3;
        if (it + 1 < niter) CP_WAIT1(); else CP_WAIT0();
        __syncthreads();
        if (it + 2 < niter) {
            const uint32_t soff = (uint32_t)(((it + 2) % 3) * ASTAGE * 4);
            #pragma unroll
            for (int i = 0; i < 2; i++) cpasync16(adst[i] + soff, asrc[i], asz[i]);
            #pragma unroll
            for (int i = 0; i < 2; i++) cpasync16(bdst[i] + soff, bsrc[i], 16);
            CP_COMMIT();
            #pragma unroll
            for (int i = 0; i < 2; i++) { asrc[i] += KC; bsrc[i] += bstep; }
        }
        // compute 2 k-steps of 8
        #pragma unroll
        for (int ks = 0; ks < KC; ks += 8) {
            uint32_t af[4][4], bf[4][2];
            #pragma unroll
            for (int mt = 0; mt < 4; mt++) {
                int r = wm + mt * 16 + g;
                af[mt][0] = __float_as_uint(As[s][r * APAD + ks + tg]);
                af[mt][1] = __float_as_uint(As[s][(r + 8) * APAD + ks + tg]);
                af[mt][2] = __float_as_uint(As[s][r * APAD + ks + tg + 4]);
                af[mt][3] = __float_as_uint(As[s][(r + 8) * APAD + ks + tg + 4]);
            }
            #pragma unroll
            for (int nt = 0; nt < 4; nt++) {
                int c = wn + nt * 8 + g;
                if (BN == 1) {
                    bf[nt][0] = f2tf32(Bs[s][c * APAD + ks + tg]);
                    bf[nt][1] = f2tf32(Bs[s][c * APAD + ks + tg + 4]);
                } else {
                    bf[nt][0] = f2tf32(Bs[s][(ks + tg) * BPADN + c]);
                    bf[nt][1] = f2tf32(Bs[s][(ks + tg + 4) * BPADN + c]);
                }
            }
            #pragma unroll
            for (int mt = 0; mt < 4; mt++)
                #pragma unroll
                for (int nt = 0; nt < 4; nt++)
                    MMA_TF32(acc[mt][nt], af[mt], bf[nt]);
        }
        __syncthreads();
    }

    // ---- epilogue ----
    #pragma unroll
    for (int mt = 0; mt < 4; mt++) {
        int rbase = mb + wm + mt * 16 + g;
        #pragma unroll
        for (int half = 0; half < 2; half++) {
            int rr = rbase + half * 8;
            if (rr >= bound) continue;
            if (EPI == 2) {
                int t = toks[e * T_TOK + rr];
                float w = wts[e * T_TOK + rr];
                float* mp = C + (size_t)t * ldc;
                #pragma unroll
                for (int nt = 0; nt < 4; nt++) {
                    int c = nb + wn + nt * 8 + 2 * tg;
                    atomicAdd(&mp[c],     w * acc[mt][nt][half * 2 + 0]);
                    atomicAdd(&mp[c + 1], w * acc[mt][nt][half * 2 + 1]);
                }
            } else {
                float sc = scale ? scale[rr] : 1.f;
                float* cp = C + (size_t)rr * ldc;
                const float* rp = res ? res + (size_t)rr * ldres : nullptr;
                #pragma unroll
                for (int nt = 0; nt < 4; nt++) {
                    int c = nb + wn + nt * 8 + 2 * tg;
                    float v0 = acc[mt][nt][half * 2 + 0];
                    float v1 = acc[mt][nt][half * 2 + 1];
                    if (bi) { v0 += bi[c - rowoff]; v1 += bi[c + 1 - rowoff]; }
                    v0 *= sc; v1 *= sc;
                    if (rp) { v0 += rp[c]; v1 += rp[c + 1]; }
                    *(float2*)&cp[c] = make_float2(v0, v1);
                }
            }
        }
    }
}

// ---------------- fused gate+up GEMM: C = tf32(silu(A@Bg)*(A@Bu)) ----------------
// Same 128x128 tiling, 2-stage cp.async, doubled B (Bg,Bu), dual accumulators.
// BN / AMODE as in mma_kernel. A pre-rounded tf32; Bg/Bu cvt'd on fragment load.
template<int BN, int AMODE>
__global__ void __launch_bounds__(256) gu_kernel(
    const float* __restrict__ A, int lda,
    const float* __restrict__ Bg, const float* __restrict__ Bu,
    int ldb, size_t strideBe,
    const int* __restrict__ toks, const int* __restrict__ counts,
    float* __restrict__ C, int ldc, size_t strideCe,
    int M, int N, int K)
{
    const int e = blockIdx.z;
    int bound = M;
    if (AMODE != 0) bound = counts[e];
    const int mb = blockIdx.y * 128;
    if (mb >= bound) return;
    const int nb = blockIdx.x * 128;
    Bg += (size_t)e * strideBe;
    Bu += (size_t)e * strideBe;
    C += (size_t)e * strideCe;

    __shared__ float As[2][ASTAGE];
    __shared__ float Bgs[2][ASTAGE];
    __shared__ float Bus[2][ASTAGE];

    const int tid = threadIdx.x;
    const int wid = tid >> 5, lane = tid & 31;
    const int g = lane >> 2, tg = lane & 3;
    const int wm = (wid & 1) * 64, wn = (wid >> 1) * 32;

    const uint32_t smA  = (uint32_t)__cvta_generic_to_shared(&As[0][0]);
    const uint32_t smBg = (uint32_t)__cvta_generic_to_shared(&Bgs[0][0]);
    const uint32_t smBu = (uint32_t)__cvta_generic_to_shared(&Bus[0][0]);

    const float* asrc[2]; int asz[2]; uint32_t adst[2];
    #pragma unroll
    for (int i = 0; i < 2; i++) {
        int id = tid + i * 256;
        int m = id >> 2, kq = id & 3;
        int gm = mb + m;
        bool valid = gm < bound;
        int row = valid ? gm : 0;
        if (AMODE == 1) row = valid ? toks[e * T_TOK + gm] : 0;
        asrc[i] = A + (size_t)row * lda + kq * 4;
        asz[i] = valid ? 16 : 0;
        adst[i] = smA + (uint32_t)(m * APAD + kq * 4) * 4u;
    }
    const float* bgsrc[2]; const float* busrc[2]; uint32_t bgdst[2], budst[2];
    long bstep;
    #pragma unroll
    for (int i = 0; i < 2; i++) {
        int id = tid + i * 256;
        if (BN == 1) {
            int n = id >> 2, kq = id & 3;
            bgsrc[i] = Bg + (size_t)(nb + n) * ldb + kq * 4;
            busrc[i] = Bu + (size_t)(nb + n) * ldb + kq * 4;
            bgdst[i] = smBg + (uint32_t)(n * APAD + kq * 4) * 4u;
            budst[i] = smBu + (uint32_t)(n * APAD + kq * 4) * 4u;
        } else {
            int kk = id >> 5, n4 = (id & 31) << 2;
            bgsrc[i] = Bg + (size_t)kk * ldb + nb + n4;
            busrc[i] = Bu + (size_t)kk * ldb + nb + n4;
            bgdst[i] = smBg + (uint32_t)(kk * BPADN + n4) * 4u;
            budst[i] = smBu + (uint32_t)(kk * BPADN + n4) * 4u;
        }
    }
    bstep = (BN == 1) ? KC : (long)KC * ldb;

    float accg[4][4][4], accu[4][4][4];
    #pragma unroll
    for (int mt = 0; mt < 4; mt++)
        #pragma unroll
        for (int nt = 0; nt < 4; nt++)
            #pragma unroll
            for (int q = 0; q < 4; q++) { accg[mt][nt][q] = 0.f; accu[mt][nt][q] = 0.f; }

    const int niter = K / KC;

    // prologue: stage 0
    #pragma unroll
    for (int i = 0; i < 2; i++) cpasync16(adst[i], asrc[i], asz[i]);
    #pragma unroll
    for (int i = 0; i < 2; i++) cpasync16(bgdst[i], bgsrc[i], 16);
    #pragma unroll
    for (int i = 0; i < 2; i++) cpasync16(budst[i], busrc[i], 16);
    CP_COMMIT();
    #pragma unroll
    for (int i = 0; i < 2; i++) { asrc[i] += KC; bgsrc[i] += bstep; busrc[i] += bstep; }

    for (int it = 0; it < niter; it++) {
        const int s = it & 1;
        CP_WAIT0();
        __syncthreads();
        if (it + 1 < niter) {
            const uint32_t soff = (uint32_t)((s ^ 1) * ASTAGE * 4);
            #pragma unroll
            for (int i = 0; i < 2; i++) cpasync16(adst[i] + soff, asrc[i], asz[i]);
            #pragma unroll
            for (int i = 0; i < 2; i++) cpasync16(bgdst[i] + soff, bgsrc[i], 16);
            #pragma unroll
            for (int i = 0; i < 2; i++) cpasync16(budst[i] + soff, busrc[i], 16);
            CP_COMMIT();
            #pragma unroll
            for (int i = 0; i < 2; i++) { asrc[i] += KC; bgsrc[i] += bstep; busrc[i] += bstep; }
        }
        #pragma unroll
        for (int ks = 0; ks < KC; ks += 8) {
            uint32_t af[4][4], bfg[4][2], bfu[4][2];
            #pragma unroll
            for (int mt = 0; mt < 4; mt++) {
                int r = wm + mt * 16 + g;
                af[mt][0] = __float_as_uint(As[s][r * APAD + ks + tg]);
                af[mt][1] = __float_as_uint(As[s][(r + 8) * APAD + ks + tg]);
                af[mt][2] = __float_as_uint(As[s][r * APAD + ks + tg + 4]);
                af[mt][3] = __float_as_uint(As[s][(r + 8) * APAD + ks + tg + 4]);
            }
            #pragma unroll
            for (int nt = 0; nt < 4; nt++) {
                int c = wn + nt * 8 + g;
                if (BN == 1) {
                    bfg[nt][0] = f2tf32(Bgs[s][c * APAD + ks + tg]);
                    bfg[nt][1] = f2tf32(Bgs[s][c * APAD + ks + tg + 4]);
                    bfu[nt][0] = f2tf32(Bus[s][c * APAD + ks + tg]);
                    bfu[nt][1] = f2tf32(Bus[s][c * APAD + ks + tg + 4]);
                } else {
                    bfg[nt][0] = f2tf32(Bgs[s][(ks + tg) * BPADN + c]);
                    bfg[nt][1] = f2tf32(Bgs[s][(ks + tg + 4) * BPADN + c]);
                    bfu[nt][0] = f2tf32(Bus[s][(ks + tg) * BPADN + c]);
                    bfu[nt][1] = f2tf32(Bus[s][(ks + tg + 4) * BPADN + c]);
                }
            }
            #pragma unroll
            for (int mt = 0; mt < 4; mt++)
                #pragma unroll
                for (int nt = 0; nt < 4; nt++) {
                    MMA_TF32(accg[mt][nt], af[mt], bfg[nt]);
                    MMA_TF32(accu[mt][nt], af[mt], bfu[nt]);
                }
        }
        __syncthreads();
    }

    // ---- epilogue: silu(g)*u, pre-rounded to tf32 (feeds next GEMM as A) ----
    #pragma unroll
    for (int mt = 0; mt < 4; mt++) {
        int rbase = mb + wm + mt * 16 + g;
        #pragma unroll
        for (int half = 0; half < 2; half++) {
            int rr = rbase + half * 8;
            if (rr >= bound) continue;
            float* cp = C + (size_t)rr * ldc;
            #pragma unroll
            for (int nt = 0; nt < 4; nt++) {
                int c = nb + wn + nt * 8 + 2 * tg;
                float g0 = accg[mt][nt][half * 2 + 0];
                float g1 = accg[mt][nt][half * 2 + 1];
                float v0 = g0 / (1.0f + expf(-g0)) * accu[mt][nt][half * 2 + 0];
                float v1 = g1 / (1.0f + expf(-g1)) * accu[mt][nt][half * 2 + 1];
                *(float2*)&cp[c] = make_float2(roundtf(v0), roundtf(v1));
            }
        }
    }
}

// ---------------- router top-k ----------------
__global__ void router_kernel(const float* __restrict__ logits, int* __restrict__ counts,
                              int* __restrict__ toks, float* __restrict__ wts) {
    int t = blockIdx.x * blockDim.x + threadIdx.x;
    if (t >= T_TOK) return;
    float v[NEXP];
    float mx = -1e30f;
    for (int e = 0; e < NEXP; e++) { v[e] = logits[t * NEXP + e]; mx = fmaxf(mx, v[e]); }
    for (int e = 0; e < NEXP; e++) v[e] = expf(v[e] - mx);
    int idx[TOPK]; float w8[TOPK]; float tw = 0.f;
    for (int j = 0; j < TOPK; j++) {
        int am = 0; float bm = -1.f;
        for (int e = 0; e < NEXP; e++) if (v[e] > bm) { bm = v[e]; am = e; }
        idx[j] = am; w8[j] = bm; tw += bm; v[am] = -2.f;
    }
    for (int j = 0; j < TOPK; j++) {
        int e = idx[j];
        int p = atomicAdd(&counts[e], 1);
        toks[e * T_TOK + p] = t;
        wts[e * T_TOK + p] = w8[j] / tw;
    }
}

// ---------------- flash attention (causal, GQA 16q/4kv, HD=64) ----------------
// QK: float4 over head-dim. PV: V stored transposed in smem, float4 over kv index.
__global__ void __launch_bounds__(256) attn_kernel(const float* __restrict__ qkv,
                                                   float* __restrict__ out) {
    const int qt = blockIdx.x, h = blockIdx.y, b = blockIdx.z;
    const int q0 = qt * 32;
    const int kvh = h >> 2;
    __shared__ float Qs[32][68];
    __shared__ float KVs[64][68];   // K row-major, then reused as V^T [d][kvrow]
    __shared__ float Ss[32][68];
    const int tid = threadIdx.x;
    const int r = tid >> 3;     // q row 0..31
    const int cth = tid & 7;    // col lane 0..7
    for (int i = tid; i < 32 * 64; i += 256) {
        int rr = i >> 6, d = i & 63;
        Qs[rr][d] = qkv[(size_t)(b * SSEQ + q0 + rr) * 1536 + h * 64 + d];
    }
    float m = -1e30f, l = 0.f;
    float oa[8];
    #pragma unroll
    for (int i = 0; i < 8; i++) oa[i] = 0.f;
    const int qg = q0 + r;
    const int ntiles = q0 / 64 + 1;
    for (int tkv = 0; tkv < ntiles; tkv++) {
        const int kb = tkv * 64;
        // K tile row-major
        for (int i = tid; i < 64 * 64; i += 256) {
            int rr = i >> 6, d = i & 63;
            KVs[rr][d] = qkv[(size_t)(b * SSEQ + kb + rr) * 1536 + 1024 + kvh * 64 + d];
        }
        __syncthreads();
        float sv[8];
        #pragma unroll
        for (int ci = 0; ci < 8; ci++) sv[ci] = 0.f;
        #pragma unroll
        for (int d4 = 0; d4 < 16; d4++) {
            float4 qv = *(const float4*)&Qs[r][d4 * 4];
            #pragma unroll
            for (int ci = 0; ci < 8; ci++) {
                int c = cth + ci * 8;
                float4 kv = *(const float4*)&KVs[c][d4 * 4];
                sv[ci] += qv.x * kv.x + qv.y * kv.y + qv.z * kv.z + qv.w * kv.w;
            }
        }
        #pragma unroll
        for (int ci = 0; ci < 8; ci++) {
            int c = cth + ci * 8;
            sv[ci] = (kb + c <= qg) ? sv[ci] * 0.125f : -1e30f;
        }
        float tmax = sv[0];
        #pragma unroll
        for (int ci = 1; ci < 8; ci++) tmax = fmaxf(tmax, sv[ci]);
        #pragma unroll
        for (int o = 4; o; o >>= 1) tmax = fmaxf(tmax, __shfl_xor_sync(0xffffffffu, tmax, o, 8));
        float newm = fmaxf(m, tmax);
        float corr = expf(m - newm);
        float ls = 0.f;
        #pragma unroll
        for (int ci = 0; ci < 8; ci++) {
            float p = expf(sv[ci] - newm);
            Ss[r][cth + ci * 8] = p;
            ls += p;
        }
        #pragma unroll
        for (int o = 4; o; o >>= 1) ls += __shfl_xor_sync(0xffffffffu, ls, o, 8);
        l = l * corr + ls;
        #pragma unroll
        for (int i = 0; i < 8; i++) oa[i] *= corr;
        m = newm;
        __syncthreads();
        // V tile TRANSPOSED: KVs[d][kvrow] = V[kvrow][d]
        for (int i = tid; i < 64 * 64; i += 256) {
            int rr = i >> 6, d = i & 63;
            KVs[d][rr] = qkv[(size_t)(b * SSEQ + kb + rr) * 1536 + 1280 + kvh * 64 + d];
        }
        __syncthreads();
        #pragma unroll
        for (int k4 = 0; k4 < 16; k4++) {
            float4 ps = *(const float4*)&Ss[r][k4 * 4];
            #pragma unroll
            for (int i = 0; i < 8; i++) {
                int c = cth + i * 8;      // output head-dim owned by this thread
                float4 vv = *(const float4*)&KVs[c][k4 * 4];
                oa[i] += ps.x * vv.x + ps.y * vv.y + ps.z * vv.z + ps.w * vv.w;
            }
        }
        __syncthreads();
    }
    float inv = 1.f / l;
    // pre-round: this buffer is A of the o-proj tensor-core GEMM
    #pragma unroll
    for (int i = 0; i < 8; i++)
        out[(size_t)(b * SSEQ + q0 + r) * 1024 + h * 64 + cth + i * 8] = roundtf(oa[i] * inv);
}

// ---------------- launch ----------------
extern "C" void kernel_launch(void* const* d_in, const int* in_sizes, int n_in,
                              void* d_out, int out_size) {
    const float* hid    = (const float*)d_in[0];
    const float* ln1    = (const float*)d_in[1];
    const float* ln2    = (const float*)d_in[2];
    const float* q_w    = (const float*)d_in[3];
    const float* q_b    = (const float*)d_in[4];
    const float* k_w    = (const float*)d_in[5];
    const float* k_b    = (const float*)d_in[6];
    const float* v_w    = (const float*)d_in[7];
    const float* v_b    = (const float*)d_in[8];
    const float* o_w    = (const float*)d_in[9];
    const float* gate_w = (const float*)d_in[10];
    const float* w_gate = (const float*)d_in[11];
    const float* w_up   = (const float*)d_in[12];
    const float* w_down = (const float*)d_in[13];
    const float* s_gate = (const float*)d_in[14];
    const float* s_up   = (const float*)d_in[15];
    const float* s_down = (const float*)d_in[16];
    const float* shg    = (const float*)d_in[17];
    float* out = (float*)d_out;

    void* pa = nullptr; cudaGetSymbolAddress(&pa, g_arena);
    void* pi = nullptr; cudaGetSymbolAddress(&pi, g_iarena);
    float* F = (float*)pa;
    int* toks = (int*)pi;
    int* counts = toks + NEXP * T_TOK;

    float* x     = F + OFF_X;
    float* qkv   = F + OFF_QKV;
    float* attn  = F + OFF_ATTN;
    float* h     = F + OFF_H;
    float* y     = F + OFF_Y;
    float* moe   = F + OFF_MOE;
    float* sint  = F + OFF_SINT;
    float* logit = F + OFF_LOG;
    float* g     = F + OFF_G;
    float* wts   = F + OFF_WTS;
    float* inter = F + OFF_INT;
    float* rtab  = F + OFF_ROPE;

    zero_counts_kernel<<<1, 64>>>(counts);
    rope_table_kernel<<<1024, 32>>>(rtab);

    // ---- attention block ----
    rmsnorm_kernel<<<T_TOK, 256>>>(hid, ln1, x);
    // fused QKV: N=1536 packed, per-column-range weight select
    mma_kernel<1, 0, 0, 1><<<dim3(12, 16, 1), 256>>>(
        x, HDIM, 0, q_w, HDIM, 0, k_w, v_w, q_b, k_b, v_b,
        nullptr, 0, nullptr, nullptr, nullptr, nullptr,
        qkv, 1536, 0, T_TOK, 1536, HDIM);
    rope_kernel<<<T_TOK, 256>>>(qkv, rtab);
    attn_kernel<<<dim3(SSEQ / 32, NHQ, BB), 256>>>(qkv, attn);
    // o-proj + residual
    mma_kernel<1, 0, 0, 0><<<dim3(8, 16, 1), 256>>>(
        attn, HDIM, 0, o_w, HDIM, 0, nullptr, nullptr, nullptr, nullptr, nullptr,
        hid, HDIM, nullptr, nullptr, nullptr, nullptr,
        h, HDIM, 0, T_TOK, 1024, HDIM);

    // ---- MoE block ----
    rmsnorm_kernel<<<T_TOK, 256>>>(h, ln2, y);
    gemm_nt_kernel<<<dim3(1, 16), 256>>>(y, HDIM, gate_w, HDIM, logit, NEXP,
                                         T_TOK, NEXP, HDIM);
    router_kernel<<<T_TOK / 256, 256>>>(logit, counts, toks, wts);

    // shared expert: fused gate+up -> sint
    gu_kernel<1, 0><<<dim3(11, 16, 1), 256>>>(
        y, HDIM, s_gate, s_up, HDIM, 0, nullptr, nullptr,
        sint, IS, 0, T_TOK, IS, HDIM);
    sgate_kernel<<<T_TOK, 256>>>(y, shg, g);
    // shared down * sigmoid-gate -> moe (writes all of moe)
    mma_kernel<1, 0, 0, 0><<<dim3(8, 16, 1), 256>>>(
        sint, IS, 0, s_down, IS, 0, nullptr, nullptr, nullptr, nullptr, nullptr,
        nullptr, 0, g, nullptr, nullptr, nullptr,
        moe, HDIM, 0, T_TOK, 1024, IS);

    // routed experts: fused gate+up -> inter, down scatter -> moe
    gu_kernel<0, 1><<<dim3(4, 16, NEXP), 256>>>(
        y, HDIM, w_gate, w_up, IE, (size_t)HDIM * IE, toks, counts,
        inter, IE, (size_t)T_TOK * IE, T_TOK, IE, HDIM);
    mma_kernel<0, 2, 2, 0><<<dim3(8, 16, NEXP), 256>>>(
        inter, IE, (size_t)T_TOK * IE, w_down, HDIM, (size_t)IE * HDIM, nullptr, nullptr,
        nullptr, nullptr, nullptr, nullptr, 0, nullptr,
        toks, counts, wts, moe, HDIM, 0, T_TOK, 1024, IE);

    // final residual
    add_kernel<<<2048, 256>>>(h, moe, out, T_TOK * HDIM);
}